// round 3
// baseline (speedup 1.0000x reference)
#include <cuda_runtime.h>
#include <cstdint>
#include <cstdio>

// ---------------------------------------------------------------------------
// EdgeVGAE encoder, algebraically collapsed:
//   S_l = segment_sum(leaky(edge_attr @ W1_l + b1_l), dst)        (edge pass)
//   h1  = leaky(deg*(x @ n1Wx + c1) + S1 @ M1),  M1 = e1W2@n1We, c1 = n1b + e1b2@n1We
//   h2  = leaky(deg*(h1 @ n2Wh + c2) + S2 @ M2)
//   mu|lv = h2 @ [muW|lvW] + [mub|lvb]
// ---------------------------------------------------------------------------

typedef unsigned long long u64;

#define NMAX 50048

__device__ float g_S1[NMAX * 128];
__device__ float g_S2[NMAX * 128];
__device__ float g_h1[NMAX * 128];
__device__ float g_h2[NMAX * 128];
__device__ float g_deg[NMAX];
__device__ float g_B1[256 * 128];
__device__ float g_B2[256 * 128];
__device__ float g_c1[128];
__device__ float g_c2[128];
__device__ float g_B3[128 * 128];
__device__ float g_b3[128];

// ---- packed f32x2 helpers --------------------------------------------------
__device__ __forceinline__ void ffma2(u64& d, u64 a, u64 b) {
    asm("fma.rn.f32x2 %0, %1, %2, %0;" : "+l"(d) : "l"(a), "l"(b));
}
__device__ __forceinline__ u64 pack2(float x, float y) {
    u64 r;
    asm("mov.b64 %0, {%1, %2};" : "=l"(r) : "f"(x), "f"(y));
    return r;
}
__device__ __forceinline__ float2 unpack2(u64 v) {
    float2 r;
    asm("mov.b64 {%0, %1}, %2;" : "=f"(r.x), "=f"(r.y) : "l"(v));
    return r;
}
__device__ __forceinline__ float lk(float v) {  // LeakyReLU(0.15)
    return fmaxf(v, 0.15f * v);
}
__device__ __forceinline__ void red4(float* p, float a, float b, float c, float d) {
    asm volatile("red.global.add.v4.f32 [%0], {%1, %2, %3, %4};"
                 :: "l"((u64)(uintptr_t)p), "f"(a), "f"(b), "f"(c), "f"(d)
                 : "memory");
}

// ---- precompute: Bcat = [nW_top ; eW2 @ nW_bot], c = nb + eb2 @ nW_bot -----
__global__ void prep_node(const float* __restrict__ eW2, const float* __restrict__ eb2,
                          const float* __restrict__ nW, const float* __restrict__ nb,
                          float* __restrict__ Bcat, float* __restrict__ c) {
    int k = blockIdx.x;   // 0..127
    int j = threadIdx.x;  // 0..127
    Bcat[k * 128 + j] = nW[k * 128 + j];
    float acc = 0.f;
    #pragma unroll 4
    for (int t = 0; t < 128; t++)
        acc += eW2[k * 128 + t] * nW[(128 + t) * 128 + j];
    Bcat[(128 + k) * 128 + j] = acc;
    if (k == 0) {
        float cc = nb[j];
        #pragma unroll 4
        for (int t = 0; t < 128; t++)
            cc += eb2[t] * nW[(128 + t) * 128 + j];
        c[j] = cc;
    }
}

// ---- precompute: B3 = [muW | lvW], b3 = [mub | lvb] ------------------------
__global__ void prep_b3(const float* __restrict__ muW, const float* __restrict__ mub,
                        const float* __restrict__ lvW, const float* __restrict__ lvb,
                        float* __restrict__ B3, float* __restrict__ b3) {
    int k = blockIdx.x, j = threadIdx.x;
    B3[k * 128 + j] = (j < 64) ? muW[k * 64 + j] : lvW[k * 64 + (j - 64)];
    if (k == 0) b3[j] = (j < 64) ? mub[j] : lvb[j - 64];
}

// ---- degree counts ---------------------------------------------------------
__global__ void deg_kernel(const int* __restrict__ dst, float* __restrict__ deg, int E) {
    int e = blockIdx.x * blockDim.x + threadIdx.x;
    if (e < E) atomicAdd(&deg[dst[e]], 1.0f);
}

// ---- fused edge pass: both layers' S accumulators in one sweep -------------
// Tile: 64 edges/block-iter. Warp = 8 edges; lane covers 4 cols of layer1 AND
// 4 cols of layer2 (conflict-free smem loads). Persistent grid-stride blocks.
__global__ __launch_bounds__(256, 2) void edge_kernel(
    const float* __restrict__ ea, const int* __restrict__ dst,
    const float* __restrict__ W1, const float* __restrict__ b1,
    const float* __restrict__ W2, const float* __restrict__ b2,
    float* __restrict__ S1, float* __restrict__ S2, int E, int ntiles) {
    extern __shared__ float sm[];
    float* shW = sm;                 // [64][256]  cols: 0..127 layer1, 128..255 layer2
    float* shA = sm + 64 * 256;      // [64][64]   k-major edge tile
    float* shBias = shA + 64 * 64;   // [256]
    int* shDst = (int*)(shBias + 256);

    const int tid = threadIdx.x;
    // stage weights (once per block)
    for (int i = tid; i < 2048; i += 256) {
        int k = i >> 5;
        int j = (i & 31) * 4;
        *(float4*)&shW[k * 256 + j]       = ((const float4*)W1)[i];
        *(float4*)&shW[k * 256 + 128 + j] = ((const float4*)W2)[i];
    }
    for (int j = tid; j < 128; j += 256) { shBias[j] = b1[j]; shBias[128 + j] = b2[j]; }
    __syncthreads();

    const int wid = tid >> 5, lane = tid & 31;
    const int j0 = lane * 4;

    for (int tile = blockIdx.x; tile < ntiles; tile += gridDim.x) {
        int e0 = tile * 64;
        __syncthreads();
        // stage 64x64 edge_attr tile transposed (conflict-free STS: lanes vary e)
        for (int i = tid; i < 1024; i += 256) {
            int e = i & 63, kq = i >> 6, k4 = kq * 4;
            float4 v = make_float4(0.f, 0.f, 0.f, 0.f);
            int ge = e0 + e;
            if (ge < E) v = *(const float4*)&ea[(size_t)ge * 64 + k4];
            shA[(k4 + 0) * 64 + e] = v.x;
            shA[(k4 + 1) * 64 + e] = v.y;
            shA[(k4 + 2) * 64 + e] = v.z;
            shA[(k4 + 3) * 64 + e] = v.w;
        }
        if (tid < 64) shDst[tid] = (e0 + tid < E) ? dst[e0 + tid] : -1;
        __syncthreads();

        u64 acc1[8][2], acc2[8][2];
        {
            float4 bb1 = *(const float4*)&shBias[j0];
            float4 bb2 = *(const float4*)&shBias[128 + j0];
            u64 i10 = pack2(bb1.x, bb1.y), i11 = pack2(bb1.z, bb1.w);
            u64 i20 = pack2(bb2.x, bb2.y), i21 = pack2(bb2.z, bb2.w);
            #pragma unroll
            for (int r = 0; r < 8; r++) {
                acc1[r][0] = i10; acc1[r][1] = i11;
                acc2[r][0] = i20; acc2[r][1] = i21;
            }
        }
        const float* aBase = shA + wid * 8;
        #pragma unroll 8
        for (int k = 0; k < 64; k++) {
            float4 a03 = *(const float4*)(aBase + k * 64);
            float4 a47 = *(const float4*)(aBase + k * 64 + 4);
            ulonglong2 w1 = *(const ulonglong2*)&shW[k * 256 + j0];
            ulonglong2 w2 = *(const ulonglong2*)&shW[k * 256 + 128 + j0];
            float a[8] = {a03.x, a03.y, a03.z, a03.w, a47.x, a47.y, a47.z, a47.w};
            #pragma unroll
            for (int r = 0; r < 8; r++) {
                u64 ad = pack2(a[r], a[r]);
                ffma2(acc1[r][0], ad, w1.x);
                ffma2(acc1[r][1], ad, w1.y);
                ffma2(acc2[r][0], ad, w2.x);
                ffma2(acc2[r][1], ad, w2.y);
            }
        }
        // leaky + scatter-add into S1/S2
        #pragma unroll
        for (int r = 0; r < 8; r++) {
            int d = shDst[wid * 8 + r];
            if (d < 0) continue;
            float2 p0 = unpack2(acc1[r][0]), p1 = unpack2(acc1[r][1]);
            float2 q0 = unpack2(acc2[r][0]), q1 = unpack2(acc2[r][1]);
            red4(&S1[(size_t)d * 128 + j0], lk(p0.x), lk(p0.y), lk(p1.x), lk(p1.y));
            red4(&S2[(size_t)d * 128 + j0], lk(q0.x), lk(q0.y), lk(q1.x), lk(q1.y));
        }
    }
}

// ---- node GEMM: out = ep(deg*(A1@B_top + bias) + A2@B_bot) -----------------
// KTOT=256/SECOND: A1 deg-scaled (k<128) + A2 (k>=128), bias*deg, leaky.
// KTOT=128/!SECOND: plain A1@B + bias, optional split (mu|logvar) store.
template <int KTOT, bool SECOND, bool DOLEAKY, bool SPLIT>
__global__ __launch_bounds__(256) void node_gemm(
    const float* __restrict__ A1, const float* __restrict__ A2,
    const float* __restrict__ B, const float* __restrict__ bias,
    const float* __restrict__ deg, float* __restrict__ out, int N) {
    extern __shared__ float sm[];
    float* shB = sm;                // [64][128]
    float* shA = sm + 64 * 128;     // [64][64]  k-major node tile

    const int tid = threadIdx.x, wid = tid >> 5, lane = tid & 31;
    const int j0 = lane * 4;
    const int row0 = blockIdx.x * 64;

    float degv[8];
    #pragma unroll
    for (int r = 0; r < 8; r++) {
        int row = row0 + wid * 8 + r;
        degv[r] = (SECOND && row < N) ? deg[row] : 1.f;
    }
    float4 bv = *(const float4*)&bias[j0];
    u64 acc[8][2];
    #pragma unroll
    for (int r = 0; r < 8; r++) {
        acc[r][0] = pack2(degv[r] * bv.x, degv[r] * bv.y);
        acc[r][1] = pack2(degv[r] * bv.z, degv[r] * bv.w);
    }

    for (int kc = 0; kc < KTOT; kc += 64) {
        __syncthreads();
        // stage B chunk [64][128]
        for (int i = tid; i < 2048; i += 256)
            *(float4*)&shB[i * 4] = *(const float4*)&B[(size_t)kc * 128 + i * 4];
        // stage A chunk transposed, deg-scaled for the A1 part
        for (int i = tid; i < 1024; i += 256) {
            int rr = i & 63, kq = i >> 6;
            int k4g = kc + kq * 4;
            int row = row0 + rr;
            float4 v = make_float4(0.f, 0.f, 0.f, 0.f);
            if (row < N) {
                if (!SECOND || k4g < 128) {
                    v = *(const float4*)&A1[(size_t)row * 128 + k4g];
                    if (SECOND) {
                        float dg = deg[row];
                        v.x *= dg; v.y *= dg; v.z *= dg; v.w *= dg;
                    }
                } else {
                    v = *(const float4*)&A2[(size_t)row * 128 + (k4g - 128)];
                }
            }
            int k4 = kq * 4;
            shA[(k4 + 0) * 64 + rr] = v.x;
            shA[(k4 + 1) * 64 + rr] = v.y;
            shA[(k4 + 2) * 64 + rr] = v.z;
            shA[(k4 + 3) * 64 + rr] = v.w;
        }
        __syncthreads();

        const float* aBase = shA + wid * 8;
        #pragma unroll 8
        for (int kk = 0; kk < 64; kk++) {
            float4 a03 = *(const float4*)(aBase + kk * 64);
            float4 a47 = *(const float4*)(aBase + kk * 64 + 4);
            ulonglong2 w = *(const ulonglong2*)&shB[kk * 128 + j0];
            float a[8] = {a03.x, a03.y, a03.z, a03.w, a47.x, a47.y, a47.z, a47.w};
            #pragma unroll
            for (int r = 0; r < 8; r++) {
                u64 ad = pack2(a[r], a[r]);
                ffma2(acc[r][0], ad, w.x);
                ffma2(acc[r][1], ad, w.y);
            }
        }
    }

    #pragma unroll
    for (int r = 0; r < 8; r++) {
        int row = row0 + wid * 8 + r;
        if (row >= N) continue;
        float2 p0 = unpack2(acc[r][0]), p1 = unpack2(acc[r][1]);
        float4 v = make_float4(p0.x, p0.y, p1.x, p1.y);
        if (DOLEAKY) { v.x = lk(v.x); v.y = lk(v.y); v.z = lk(v.z); v.w = lk(v.w); }
        if (!SPLIT) {
            *(float4*)&out[(size_t)row * 128 + j0] = v;
        } else {
            if (j0 < 64)
                *(float4*)&out[(size_t)row * 64 + j0] = v;
            else
                *(float4*)&out[(size_t)N * 64 + (size_t)row * 64 + (j0 - 64)] = v;
        }
    }
}

// ---------------------------------------------------------------------------
extern "C" void kernel_launch(void* const* d_in, const int* in_sizes, int n_in,
                              void* d_out, int out_size) {
    const float* x    = (const float*)d_in[0];
    const int*   ei   = (const int*)d_in[1];
    const float* ea   = (const float*)d_in[2];
    const float* e1W1 = (const float*)d_in[3];
    const float* e1b1 = (const float*)d_in[4];
    const float* e1W2 = (const float*)d_in[5];
    const float* e1b2 = (const float*)d_in[6];
    const float* n1W  = (const float*)d_in[7];
    const float* n1b  = (const float*)d_in[8];
    const float* e2W1 = (const float*)d_in[9];
    const float* e2b1 = (const float*)d_in[10];
    const float* e2W2 = (const float*)d_in[11];
    const float* e2b2 = (const float*)d_in[12];
    const float* n2W  = (const float*)d_in[13];
    const float* n2b  = (const float*)d_in[14];
    const float* muW  = (const float*)d_in[15];
    const float* mub  = (const float*)d_in[16];
    const float* lvW  = (const float*)d_in[17];
    const float* lvb  = (const float*)d_in[18];

    const int N = in_sizes[0] / 128;  // 50000
    const int E = in_sizes[2] / 64;   // 640000
    const int* dst = ei + E;          // edge_index row 1

    float *S1, *S2, *h1, *h2, *dg, *B1, *B2, *c1, *c2, *B3, *b3;
    cudaGetSymbolAddress((void**)&S1, g_S1);
    cudaGetSymbolAddress((void**)&S2, g_S2);
    cudaGetSymbolAddress((void**)&h1, g_h1);
    cudaGetSymbolAddress((void**)&h2, g_h2);
    cudaGetSymbolAddress((void**)&dg, g_deg);
    cudaGetSymbolAddress((void**)&B1, g_B1);
    cudaGetSymbolAddress((void**)&B2, g_B2);
    cudaGetSymbolAddress((void**)&c1, g_c1);
    cudaGetSymbolAddress((void**)&c2, g_c2);
    cudaGetSymbolAddress((void**)&B3, g_B3);
    cudaGetSymbolAddress((void**)&b3, g_b3);

    cudaMemsetAsync(S1, 0, (size_t)N * 128 * sizeof(float));
    cudaMemsetAsync(S2, 0, (size_t)N * 128 * sizeof(float));
    cudaMemsetAsync(dg, 0, (size_t)N * sizeof(float));

    prep_node<<<128, 128>>>(e1W2, e1b2, n1W, n1b, B1, c1);
    prep_node<<<128, 128>>>(e2W2, e2b2, n2W, n2b, B2, c2);
    prep_b3<<<128, 128>>>(muW, mub, lvW, lvb, B3, b3);
    deg_kernel<<<(E + 255) / 256, 256>>>(dst, dg, E);

    const int EDGE_SMEM = (64 * 256 + 64 * 64 + 256) * 4 + 64 * 4;  // 83200 B
    cudaFuncSetAttribute(edge_kernel, cudaFuncAttributeMaxDynamicSharedMemorySize, EDGE_SMEM);
    int ntiles = (E + 63) / 64;
    int egrid = ntiles < 304 ? ntiles : 304;
    edge_kernel<<<egrid, 256, EDGE_SMEM>>>(ea, dst, e1W1, e1b1, e2W1, e2b1, S1, S2, E, ntiles);

    const int NODE_SMEM = (64 * 128 + 64 * 64) * 4;  // 49152 B
    int nblk = (N + 63) / 64;
    cudaFuncSetAttribute(node_gemm<256, true, true, false>,
                         cudaFuncAttributeMaxDynamicSharedMemorySize, NODE_SMEM);
    cudaFuncSetAttribute(node_gemm<128, false, false, true>,
                         cudaFuncAttributeMaxDynamicSharedMemorySize, NODE_SMEM);

    node_gemm<256, true, true, false><<<nblk, 256, NODE_SMEM>>>(x,  S1, B1, c1, dg, h1, N);
    node_gemm<256, true, true, false><<<nblk, 256, NODE_SMEM>>>(h1, S2, B2, c2, dg, h2, N);
    node_gemm<128, false, false, true><<<nblk, 256, NODE_SMEM>>>(h2, nullptr, B3, b3, nullptr,
                                                                 (float*)d_out, N);
}

// round 5
// speedup vs baseline: 1.1374x; 1.1374x over previous
#include <cuda_runtime.h>
#include <cuda_bf16.h>
#include <cstdint>
#include <cstdio>

// ---------------------------------------------------------------------------
// EdgeVGAE encoder, algebraically collapsed:
//   S_l = segment_sum(leaky(edge_attr @ W1_l + b1_l), dst)   (edge pass, l=1,2)
//   h1  = leaky(deg*(x @ n1Wx + c1) + S1 @ M1)
//   h2  = leaky(deg*(h1 @ n2Wh + c2) + S2 @ M2)
//   mu|lv = h2 @ [muW|lvW] + [mub|lvb]
// Edge pass on mma.sync bf16 (split hi/lo, 3 MMAs = ~fp32 precision).
// tcgen05 is rejected by this toolchain (PTX target sm_103, not sm_103a).
// ---------------------------------------------------------------------------

typedef unsigned long long u64;

#define NMAX 50048

__device__ float g_S1[NMAX * 128];
__device__ float g_S2[NMAX * 128];
__device__ float g_h1[NMAX * 128];
__device__ float g_h2[NMAX * 128];
__device__ float g_deg[NMAX];
__device__ float g_B1[256 * 128];
__device__ float g_B2[256 * 128];
__device__ float g_c1[128];
__device__ float g_c2[128];
__device__ float g_B3[128 * 128];
__device__ float g_b3[128];
__device__ __nv_bfloat16 g_Bth[256 * 64];
__device__ __nv_bfloat16 g_Btl[256 * 64];
__device__ float g_biascat[256];

// ============================ helpers ======================================
__device__ __forceinline__ void ffma2(u64& d, u64 a, u64 b) {
    asm("fma.rn.f32x2 %0, %1, %2, %0;" : "+l"(d) : "l"(a), "l"(b));
}
__device__ __forceinline__ u64 pack2(float x, float y) {
    u64 r;
    asm("mov.b64 %0, {%1, %2};" : "=l"(r) : "f"(x), "f"(y));
    return r;
}
__device__ __forceinline__ float2 unpack2(u64 v) {
    float2 r;
    asm("mov.b64 {%0, %1}, %2;" : "=f"(r.x), "=f"(r.y) : "l"(v));
    return r;
}
__device__ __forceinline__ float lk(float v) { return fmaxf(v, 0.15f * v); }
__device__ __forceinline__ void red4(float* p, float a, float b, float c, float d) {
    asm volatile("red.global.add.v4.f32 [%0], {%1, %2, %3, %4};"
                 :: "l"((u64)(uintptr_t)p), "f"(a), "f"(b), "f"(c), "f"(d) : "memory");
}

// mma.sync m16n8k16 bf16 -> f32, D == C (accumulate in place)
__device__ __forceinline__ void mma16816(float* c, const uint32_t* a,
                                         uint32_t b0, uint32_t b1) {
    asm volatile(
        "mma.sync.aligned.m16n8k16.row.col.f32.bf16.bf16.f32 "
        "{%0,%1,%2,%3}, {%4,%5,%6,%7}, {%8,%9}, {%0,%1,%2,%3};"
        : "+f"(c[0]), "+f"(c[1]), "+f"(c[2]), "+f"(c[3])
        : "r"(a[0]), "r"(a[1]), "r"(a[2]), "r"(a[3]), "r"(b0), "r"(b1));
}

// ======================= precompute kernels ================================
__global__ void prep_node(const float* __restrict__ eW2, const float* __restrict__ eb2,
                          const float* __restrict__ nW, const float* __restrict__ nb,
                          float* __restrict__ Bcat, float* __restrict__ c) {
    int k = blockIdx.x, j = threadIdx.x;
    Bcat[k * 128 + j] = nW[k * 128 + j];
    float acc = 0.f;
    #pragma unroll 4
    for (int t = 0; t < 128; t++) acc += eW2[k * 128 + t] * nW[(128 + t) * 128 + j];
    Bcat[(128 + k) * 128 + j] = acc;
    if (k == 0) {
        float cc = nb[j];
        #pragma unroll 4
        for (int t = 0; t < 128; t++) cc += eb2[t] * nW[(128 + t) * 128 + j];
        c[j] = cc;
    }
}

__global__ void prep_b3(const float* __restrict__ muW, const float* __restrict__ mub,
                        const float* __restrict__ lvW, const float* __restrict__ lvb,
                        float* __restrict__ B3, float* __restrict__ b3) {
    int k = blockIdx.x, j = threadIdx.x;
    B3[k * 128 + j] = (j < 64) ? muW[k * 64 + j] : lvW[k * 64 + (j - 64)];
    if (k == 0) b3[j] = (j < 64) ? mub[j] : lvb[j - 64];
}

// Bt[n][k] = W_l[k][n] (n<128 -> layer1, else layer2), split hi/lo bf16.
__global__ void prep_bt(const float* __restrict__ W1, const float* __restrict__ b1,
                        const float* __restrict__ W2, const float* __restrict__ b2,
                        __nv_bfloat16* __restrict__ bth, __nv_bfloat16* __restrict__ btl,
                        float* __restrict__ bias) {
    int n = blockIdx.x, k = threadIdx.x;  // n in [0,256), k in [0,64)
    float w = (n < 128) ? W1[k * 128 + n] : W2[k * 128 + (n - 128)];
    __nv_bfloat16 h = __float2bfloat16(w);
    float r = w - __bfloat162float(h);
    bth[n * 64 + k] = h;
    btl[n * 64 + k] = __float2bfloat16(r);
    if (k == 0) bias[n] = (n < 128) ? b1[n] : b2[n - 128];
}

__global__ void deg_kernel(const int* __restrict__ dst, float* __restrict__ deg, int E) {
    int e = blockIdx.x * blockDim.x + threadIdx.x;
    if (e < E) atomicAdd(&deg[dst[e]], 1.0f);
}

// ======================= mma.sync edge pass ================================
// Tile: 128 edges (M) x 256 cols (N = S1|S2) x K=64.
// Warp w owns N-slice [w*32, w*32+32): acc = 8 m-tiles x 4 n-tiles x 4 f32.
// A (edges, hi+lo bf16) staged per-tile in smem with 72-element padded rows
// (conflict-free 32-bit frag loads). B (weights^T, hi+lo) staged once.
// Split-bf16: D += Ah*Bh + Al*Bh + Ah*Bl  (drop Al*Bl ~ 2^-18).
// Epilogue: bias + leaky, quad-shuffle pack -> 2 red4 per edge.
#define EPAD_B 144  // 72 bf16 per row
#define SM_BH 0
#define SM_BL 36864
#define SM_AH 73728
#define SM_AL 92160
#define SM_BIAS 110592
#define SM_DST 111616
#define EDGE_SMEM 112640

__global__ __launch_bounds__(256, 1)
void edge_mma_kernel(const float* __restrict__ ea, const int* __restrict__ dstv,
                     const __nv_bfloat16* __restrict__ Bth,
                     const __nv_bfloat16* __restrict__ Btl,
                     const float* __restrict__ biascat,
                     float* __restrict__ S1, float* __restrict__ S2,
                     int E, int ntiles) {
    extern __shared__ __align__(16) char smc[];
    char* sBh = smc + SM_BH;
    char* sBl = smc + SM_BL;
    char* sAh = smc + SM_AH;
    char* sAl = smc + SM_AL;
    float* sBias = (float*)(smc + SM_BIAS);
    int* sDst = (int*)(smc + SM_DST);

    const int tid = threadIdx.x;
    const int wid = tid >> 5, lane = tid & 31;
    const int g = lane >> 2, q = lane & 3;

    // Stage B (padded) + bias once per block.
    for (int i = tid; i < 8192; i += 256) {
        int n = i >> 5, kk = i & 31;  // kk in u32 (= 2 bf16) units
        *(uint32_t*)(sBh + n * EPAD_B + kk * 4) = ((const uint32_t*)Bth)[n * 32 + kk];
        *(uint32_t*)(sBl + n * EPAD_B + kk * 4) = ((const uint32_t*)Btl)[n * 32 + kk];
    }
    sBias[tid] = biascat[tid];

    const int n0 = wid * 32;

    for (int tile = blockIdx.x; tile < ntiles; tile += gridDim.x) {
        const int e0 = tile * 128;
        // ---- stage A tile (hi/lo split) ----
        {
            const int row = tid >> 1, hf = tid & 1;
            const int ge = e0 + row;
            uint32_t* ah = (uint32_t*)(sAh + row * EPAD_B + hf * 64);
            uint32_t* al = (uint32_t*)(sAl + row * EPAD_B + hf * 64);
            if (ge < E) {
                const float4* src = (const float4*)(ea + (size_t)ge * 64 + hf * 32);
                #pragma unroll
                for (int j = 0; j < 8; j++) {
                    float4 v = src[j];
                    __nv_bfloat162 h0 = __floats2bfloat162_rn(v.x, v.y);
                    __nv_bfloat162 h1 = __floats2bfloat162_rn(v.z, v.w);
                    __nv_bfloat162 l0 = __floats2bfloat162_rn(v.x - __low2float(h0),
                                                              v.y - __high2float(h0));
                    __nv_bfloat162 l1 = __floats2bfloat162_rn(v.z - __low2float(h1),
                                                              v.w - __high2float(h1));
                    ah[j * 2]     = *(uint32_t*)&h0;
                    ah[j * 2 + 1] = *(uint32_t*)&h1;
                    al[j * 2]     = *(uint32_t*)&l0;
                    al[j * 2 + 1] = *(uint32_t*)&l1;
                }
            } else {
                #pragma unroll
                for (int j = 0; j < 16; j++) { ah[j] = 0u; al[j] = 0u; }
            }
            if (hf == 0) sDst[row] = (ge < E) ? dstv[ge] : -1;
        }
        __syncthreads();

        // ---- mainloop ----
        float acc[8][4][4];
        #pragma unroll
        for (int mt = 0; mt < 8; mt++)
            #pragma unroll
            for (int nt = 0; nt < 4; nt++)
                #pragma unroll
                for (int i = 0; i < 4; i++) acc[mt][nt][i] = 0.f;

        #pragma unroll
        for (int nt = 0; nt < 4; nt++) {
            const char* bhRow = sBh + (n0 + nt * 8 + g) * EPAD_B;
            const char* blRow = sBl + (n0 + nt * 8 + g) * EPAD_B;
            uint32_t bh[4][2], bl[4][2];
            #pragma unroll
            for (int kt = 0; kt < 4; kt++) {
                int kb = (kt * 16 + q * 2) * 2;  // byte offset
                bh[kt][0] = *(const uint32_t*)(bhRow + kb);
                bh[kt][1] = *(const uint32_t*)(bhRow + kb + 16);
                bl[kt][0] = *(const uint32_t*)(blRow + kb);
                bl[kt][1] = *(const uint32_t*)(blRow + kb + 16);
            }
            #pragma unroll
            for (int mt = 0; mt < 8; mt++) {
                const char* aLo = sAh + (mt * 16 + g) * EPAD_B;
                const char* aHi = aLo + 8 * EPAD_B;
                const char* cLo = sAl + (mt * 16 + g) * EPAD_B;
                const char* cHi = cLo + 8 * EPAD_B;
                #pragma unroll
                for (int kt = 0; kt < 4; kt++) {
                    int kb = (kt * 16 + q * 2) * 2;
                    uint32_t a[4], al4[4];
                    a[0] = *(const uint32_t*)(aLo + kb);
                    a[1] = *(const uint32_t*)(aHi + kb);
                    a[2] = *(const uint32_t*)(aLo + kb + 16);
                    a[3] = *(const uint32_t*)(aHi + kb + 16);
                    al4[0] = *(const uint32_t*)(cLo + kb);
                    al4[1] = *(const uint32_t*)(cHi + kb);
                    al4[2] = *(const uint32_t*)(cLo + kb + 16);
                    al4[3] = *(const uint32_t*)(cHi + kb + 16);
                    mma16816(acc[mt][nt], a, bh[kt][0], bh[kt][1]);
                    mma16816(acc[mt][nt], al4, bh[kt][0], bh[kt][1]);
                    mma16816(acc[mt][nt], a, bl[kt][0], bl[kt][1]);
                }
            }
        }

        // ---- epilogue: bias + leaky + quad-pack + red4 scatter ----
        #pragma unroll
        for (int mt = 0; mt < 8; mt++) {
            const int rowLo = mt * 16 + g;
            const int dLo = sDst[rowLo], dHi = sDst[rowLo + 8];
            #pragma unroll
            for (int nt = 0; nt < 4; nt++) {
                float* c = acc[mt][nt];
                const int col = n0 + nt * 8 + q * 2;
                const float b0 = sBias[col], b1 = sBias[col + 1];
                float v0 = lk(c[0] + b0), v1 = lk(c[1] + b1);
                float v2 = lk(c[2] + b0), v3 = lk(c[3] + b1);
                float r0 = __shfl_xor_sync(0xffffffffu, v0, 1);
                float r1 = __shfl_xor_sync(0xffffffffu, v1, 1);
                float r2 = __shfl_xor_sync(0xffffffffu, v2, 1);
                float r3 = __shfl_xor_sync(0xffffffffu, v3, 1);
                const int colb = n0 + nt * 8 + (q >> 1) * 4;
                int d;
                float w0, w1, w2, w3;
                if ((q & 1) == 0) { d = dLo; w0 = v0; w1 = v1; w2 = r0; w3 = r1; }
                else              { d = dHi; w0 = r2; w1 = r3; w2 = v2; w3 = v3; }
                if (d >= 0) {
                    float* Sp = (n0 < 128) ? (S1 + (size_t)d * 128 + colb)
                                           : (S2 + (size_t)d * 128 + (colb - 128));
                    red4(Sp, w0, w1, w2, w3);
                }
            }
        }
        __syncthreads();
    }
}

// ======================= node GEMMs (fp32, known-good) =====================
template <int KTOT, bool SECOND, bool DOLEAKY, bool SPLIT>
__global__ __launch_bounds__(256) void node_gemm(
    const float* __restrict__ A1, const float* __restrict__ A2,
    const float* __restrict__ B, const float* __restrict__ bias,
    const float* __restrict__ deg, float* __restrict__ out, int N) {
    extern __shared__ float sm[];
    float* shB = sm;             // [64][128]
    float* shA = sm + 64 * 128;  // [64][64]

    const int tid = threadIdx.x, wid = tid >> 5, lane = tid & 31;
    const int j0 = lane * 4;
    const int row0 = blockIdx.x * 64;

    float degv[8];
    #pragma unroll
    for (int r = 0; r < 8; r++) {
        int row = row0 + wid * 8 + r;
        degv[r] = (SECOND && row < N) ? deg[row] : 1.f;
    }
    float4 bv = *(const float4*)&bias[j0];
    u64 acc[8][2];
    #pragma unroll
    for (int r = 0; r < 8; r++) {
        acc[r][0] = pack2(degv[r] * bv.x, degv[r] * bv.y);
        acc[r][1] = pack2(degv[r] * bv.z, degv[r] * bv.w);
    }

    for (int kc = 0; kc < KTOT; kc += 64) {
        __syncthreads();
        for (int i = tid; i < 2048; i += 256)
            *(float4*)&shB[i * 4] = *(const float4*)&B[(size_t)kc * 128 + i * 4];
        for (int i = tid; i < 1024; i += 256) {
            int rr = i & 63, kq = i >> 6;
            int k4g = kc + kq * 4;
            int row = row0 + rr;
            float4 v = make_float4(0.f, 0.f, 0.f, 0.f);
            if (row < N) {
                if (!SECOND || k4g < 128) {
                    v = *(const float4*)&A1[(size_t)row * 128 + k4g];
                    if (SECOND) {
                        float dg = deg[row];
                        v.x *= dg; v.y *= dg; v.z *= dg; v.w *= dg;
                    }
                } else {
                    v = *(const float4*)&A2[(size_t)row * 128 + (k4g - 128)];
                }
            }
            int k4 = kq * 4;
            shA[(k4 + 0) * 64 + rr] = v.x;
            shA[(k4 + 1) * 64 + rr] = v.y;
            shA[(k4 + 2) * 64 + rr] = v.z;
            shA[(k4 + 3) * 64 + rr] = v.w;
        }
        __syncthreads();

        const float* aBase = shA + wid * 8;
        #pragma unroll 8
        for (int kk = 0; kk < 64; kk++) {
            float4 a03 = *(const float4*)(aBase + kk * 64);
            float4 a47 = *(const float4*)(aBase + kk * 64 + 4);
            ulonglong2 w = *(const ulonglong2*)&shB[kk * 128 + j0];
            float a[8] = {a03.x, a03.y, a03.z, a03.w, a47.x, a47.y, a47.z, a47.w};
            #pragma unroll
            for (int r = 0; r < 8; r++) {
                u64 ad = pack2(a[r], a[r]);
                ffma2(acc[r][0], ad, w.x);
                ffma2(acc[r][1], ad, w.y);
            }
        }
    }

    #pragma unroll
    for (int r = 0; r < 8; r++) {
        int row = row0 + wid * 8 + r;
        if (row >= N) continue;
        float2 p0 = unpack2(acc[r][0]), p1 = unpack2(acc[r][1]);
        float4 v = make_float4(p0.x, p0.y, p1.x, p1.y);
        if (DOLEAKY) { v.x = lk(v.x); v.y = lk(v.y); v.z = lk(v.z); v.w = lk(v.w); }
        if (!SPLIT) {
            *(float4*)&out[(size_t)row * 128 + j0] = v;
        } else {
            if (j0 < 64)
                *(float4*)&out[(size_t)row * 64 + j0] = v;
            else
                *(float4*)&out[(size_t)N * 64 + (size_t)row * 64 + (j0 - 64)] = v;
        }
    }
}

// ---------------------------------------------------------------------------
extern "C" void kernel_launch(void* const* d_in, const int* in_sizes, int n_in,
                              void* d_out, int out_size) {
    const float* x    = (const float*)d_in[0];
    const int*   ei   = (const int*)d_in[1];
    const float* ea   = (const float*)d_in[2];
    const float* e1W1 = (const float*)d_in[3];
    const float* e1b1 = (const float*)d_in[4];
    const float* e1W2 = (const float*)d_in[5];
    const float* e1b2 = (const float*)d_in[6];
    const float* n1W  = (const float*)d_in[7];
    const float* n1b  = (const float*)d_in[8];
    const float* e2W1 = (const float*)d_in[9];
    const float* e2b1 = (const float*)d_in[10];
    const float* e2W2 = (const float*)d_in[11];
    const float* e2b2 = (const float*)d_in[12];
    const float* n2W  = (const float*)d_in[13];
    const float* n2b  = (const float*)d_in[14];
    const float* muW  = (const float*)d_in[15];
    const float* mub  = (const float*)d_in[16];
    const float* lvW  = (const float*)d_in[17];
    const float* lvb  = (const float*)d_in[18];

    const int N = in_sizes[0] / 128;  // 50000
    const int E = in_sizes[2] / 64;   // 640000
    const int* dst = ei + E;          // edge_index row 1

    float *S1, *S2, *h1, *h2, *dg, *B1, *B2, *c1, *c2, *B3, *b3, *biascat;
    __nv_bfloat16 *Bth, *Btl;
    cudaGetSymbolAddress((void**)&S1, g_S1);
    cudaGetSymbolAddress((void**)&S2, g_S2);
    cudaGetSymbolAddress((void**)&h1, g_h1);
    cudaGetSymbolAddress((void**)&h2, g_h2);
    cudaGetSymbolAddress((void**)&dg, g_deg);
    cudaGetSymbolAddress((void**)&B1, g_B1);
    cudaGetSymbolAddress((void**)&B2, g_B2);
    cudaGetSymbolAddress((void**)&c1, g_c1);
    cudaGetSymbolAddress((void**)&c2, g_c2);
    cudaGetSymbolAddress((void**)&B3, g_B3);
    cudaGetSymbolAddress((void**)&b3, g_b3);
    cudaGetSymbolAddress((void**)&Bth, g_Bth);
    cudaGetSymbolAddress((void**)&Btl, g_Btl);
    cudaGetSymbolAddress((void**)&biascat, g_biascat);

    cudaMemsetAsync(S1, 0, (size_t)N * 128 * sizeof(float));
    cudaMemsetAsync(S2, 0, (size_t)N * 128 * sizeof(float));
    cudaMemsetAsync(dg, 0, (size_t)N * sizeof(float));

    prep_node<<<128, 128>>>(e1W2, e1b2, n1W, n1b, B1, c1);
    prep_node<<<128, 128>>>(e2W2, e2b2, n2W, n2b, B2, c2);
    prep_b3<<<128, 128>>>(muW, mub, lvW, lvb, B3, b3);
    prep_bt<<<256, 64>>>(e1W1, e1b1, e2W1, e2b1, Bth, Btl, biascat);
    deg_kernel<<<(E + 255) / 256, 256>>>(dst, dg, E);

    // mma.sync edge pass
    cudaFuncSetAttribute(edge_mma_kernel, cudaFuncAttributeMaxDynamicSharedMemorySize,
                         EDGE_SMEM);
    int ntiles = (E + 127) / 128;
    int egrid = ntiles < 148 ? ntiles : 148;
    edge_mma_kernel<<<egrid, 256, EDGE_SMEM>>>(ea, dst, Bth, Btl, biascat, S1, S2, E, ntiles);

    const int NODE_SMEM = (64 * 128 + 64 * 64) * 4;  // 49152 B
    int nblk = (N + 63) / 64;
    cudaFuncSetAttribute(node_gemm<256, true, true, false>,
                         cudaFuncAttributeMaxDynamicSharedMemorySize, NODE_SMEM);
    cudaFuncSetAttribute(node_gemm<128, false, false, true>,
                         cudaFuncAttributeMaxDynamicSharedMemorySize, NODE_SMEM);

    node_gemm<256, true, true, false><<<nblk, 256, NODE_SMEM>>>(x,  S1, B1, c1, dg, h1, N);
    node_gemm<256, true, true, false><<<nblk, 256, NODE_SMEM>>>(h1, S2, B2, c2, dg, h2, N);
    node_gemm<128, false, false, true><<<nblk, 256, NODE_SMEM>>>(h2, nullptr, B3, b3, nullptr,
                                                                 (float*)d_out, N);
}

// round 6
// speedup vs baseline: 1.1928x; 1.0487x over previous
#include <cuda_runtime.h>
#include <cuda_bf16.h>
#include <cstdint>
#include <cstdio>

// ---------------------------------------------------------------------------
// EdgeVGAE encoder, algebraically collapsed:
//   S_l = segment_sum(leaky(edge_attr @ W1_l + b1_l), dst)   (edge pass, l=1,2)
//   h1  = leaky(deg*(x @ n1Wx + c1) + S1 @ M1)
//   h2  = leaky(deg*(h1 @ n2Wh + c2) + S2 @ M2)
//   mu|lv = h2 @ [muW|lvW] + [mub|lvb]
// Edge pass: mma.sync bf16 split hi/lo (3 MMAs ~ fp32 precision).
// R6: B fragments register-resident (kills 8-way LDS conflicts), A via
// ldmatrix.x4 with A-hoisted loop (kills 4x A reload), preps merged.
// ---------------------------------------------------------------------------

typedef unsigned long long u64;

#define NMAX 50048

__device__ float g_S1[NMAX * 128];
__device__ float g_S2[NMAX * 128];
__device__ float g_h1[NMAX * 128];
__device__ float g_h2[NMAX * 128];
__device__ float g_deg[NMAX];
__device__ float g_B1[256 * 128];
__device__ float g_B2[256 * 128];
__device__ float g_c1[128];
__device__ float g_c2[128];
__device__ float g_B3[128 * 128];
__device__ float g_b3[128];
__device__ __nv_bfloat16 g_Bth[256 * 64];
__device__ __nv_bfloat16 g_Btl[256 * 64];
__device__ float g_biascat[256];

// ============================ helpers ======================================
__device__ __forceinline__ uint32_t smem_u32(const void* p) {
    uint32_t a;
    asm("{ .reg .u64 t; cvta.to.shared.u64 t, %1; cvt.u32.u64 %0, t; }" : "=r"(a) : "l"(p));
    return a;
}
__device__ __forceinline__ void ffma2(u64& d, u64 a, u64 b) {
    asm("fma.rn.f32x2 %0, %1, %2, %0;" : "+l"(d) : "l"(a), "l"(b));
}
__device__ __forceinline__ u64 pack2(float x, float y) {
    u64 r;
    asm("mov.b64 %0, {%1, %2};" : "=l"(r) : "f"(x), "f"(y));
    return r;
}
__device__ __forceinline__ float2 unpack2(u64 v) {
    float2 r;
    asm("mov.b64 {%0, %1}, %2;" : "=f"(r.x), "=f"(r.y) : "l"(v));
    return r;
}
__device__ __forceinline__ float lk(float v) { return fmaxf(v, 0.15f * v); }
__device__ __forceinline__ void red4(float* p, float a, float b, float c, float d) {
    asm volatile("red.global.add.v4.f32 [%0], {%1, %2, %3, %4};"
                 :: "l"((u64)(uintptr_t)p), "f"(a), "f"(b), "f"(c), "f"(d) : "memory");
}

// mma.sync m16n8k16 bf16 -> f32, accumulate in place
__device__ __forceinline__ void mma16816(float* c, const uint32_t* a,
                                         uint32_t b0, uint32_t b1) {
    asm volatile(
        "mma.sync.aligned.m16n8k16.row.col.f32.bf16.bf16.f32 "
        "{%0,%1,%2,%3}, {%4,%5,%6,%7}, {%8,%9}, {%0,%1,%2,%3};"
        : "+f"(c[0]), "+f"(c[1]), "+f"(c[2]), "+f"(c[3])
        : "r"(a[0]), "r"(a[1]), "r"(a[2]), "r"(a[3]), "r"(b0), "r"(b1));
}

__device__ __forceinline__ void ldsm_x4(uint32_t* r, uint32_t addr) {
    asm volatile("ldmatrix.sync.aligned.m8n8.x4.shared.b16 {%0,%1,%2,%3}, [%4];"
                 : "=r"(r[0]), "=r"(r[1]), "=r"(r[2]), "=r"(r[3]) : "r"(addr));
}

// ======================= merged precompute =================================
__global__ void prep_all(const float* __restrict__ e1W2, const float* __restrict__ e1b2,
                         const float* __restrict__ n1W,  const float* __restrict__ n1b,
                         const float* __restrict__ e2W2, const float* __restrict__ e2b2,
                         const float* __restrict__ n2W,  const float* __restrict__ n2b,
                         const float* __restrict__ muW,  const float* __restrict__ mub,
                         const float* __restrict__ lvW,  const float* __restrict__ lvb,
                         const float* __restrict__ e1W1, const float* __restrict__ e1b1,
                         const float* __restrict__ e2W1, const float* __restrict__ e2b1,
                         float* __restrict__ B1, float* __restrict__ c1,
                         float* __restrict__ B2, float* __restrict__ c2,
                         float* __restrict__ B3, float* __restrict__ b3,
                         __nv_bfloat16* __restrict__ bth, __nv_bfloat16* __restrict__ btl,
                         float* __restrict__ bias) {
    const int task = blockIdx.y, bx = blockIdx.x, tid = threadIdx.x;
    if (task <= 1) {
        const float* eW2 = task ? e2W2 : e1W2;
        const float* eb2 = task ? e2b2 : e1b2;
        const float* nW  = task ? n2W  : n1W;
        const float* nb  = task ? n2b  : n1b;
        float* Bcat = task ? B2 : B1;
        float* c = task ? c2 : c1;
        int k = bx, j = tid;
        Bcat[k * 128 + j] = nW[k * 128 + j];
        float acc = 0.f;
        #pragma unroll 4
        for (int t = 0; t < 128; t++) acc += eW2[k * 128 + t] * nW[(128 + t) * 128 + j];
        Bcat[(128 + k) * 128 + j] = acc;
        if (k == 0) {
            float cc = nb[j];
            #pragma unroll 4
            for (int t = 0; t < 128; t++) cc += eb2[t] * nW[(128 + t) * 128 + j];
            c[j] = cc;
        }
    } else if (task == 2) {
        int k = bx, j = tid;
        B3[k * 128 + j] = (j < 64) ? muW[k * 64 + j] : lvW[k * 64 + (j - 64)];
        if (k == 0) b3[j] = (j < 64) ? mub[j] : lvb[j - 64];
    } else {
        int k = tid & 63, half = tid >> 6;
        int n = bx + half * 128;
        float w = (n < 128) ? e1W1[k * 128 + n] : e2W1[k * 128 + (n - 128)];
        __nv_bfloat16 h = __float2bfloat16(w);
        float r = w - __bfloat162float(h);
        bth[n * 64 + k] = h;
        btl[n * 64 + k] = __float2bfloat16(r);
        if (k == 0) bias[n] = (n < 128) ? e1b1[n] : e2b1[n - 128];
    }
}

__global__ void deg_kernel(const int* __restrict__ dst, float* __restrict__ deg, int E) {
    int e = blockIdx.x * blockDim.x + threadIdx.x;
    if (e < E) atomicAdd(&deg[dst[e]], 1.0f);
}

// ======================= mma.sync edge pass ================================
// Tile: 128 edges (M) x 256 cols (N = S1|S2) x K=64.
// Warp w owns N-slice [w*32, w*32+32). B fragments (hi+lo) register-resident,
// loaded from GMEM once. A staged hi/lo bf16 in SMEM (144B pitch), fragments
// via ldmatrix.x4, hoisted across the 4 n-tiles.
// Split-bf16: D += Ah*Bh + Al*Bh + Ah*Bl  (drop Al*Bl ~ 2^-16).
#define APITCH 144

__global__ __launch_bounds__(256, 1)
void edge_mma_kernel(const float* __restrict__ ea, const int* __restrict__ dstv,
                     const __nv_bfloat16* __restrict__ Bth,
                     const __nv_bfloat16* __restrict__ Btl,
                     const float* __restrict__ biascat,
                     float* __restrict__ S1, float* __restrict__ S2,
                     int E, int ntiles) {
    __shared__ __align__(16) char sA[2 * 128 * APITCH];  // hi | lo
    __shared__ float sBias[256];
    __shared__ int sDst[128];
    char* sAh = sA;
    char* sAl = sA + 128 * APITCH;

    const int tid = threadIdx.x, wid = tid >> 5, lane = tid & 31;
    const int g = lane >> 2, q = lane & 3;
    const int n0 = wid * 32;

    sBias[tid] = biascat[tid];

    // ---- B fragments in registers (once) ----
    uint32_t bh[4][4][2], bl[4][4][2];
    {
        const uint32_t* BH = (const uint32_t*)Bth;
        const uint32_t* BL = (const uint32_t*)Btl;
        #pragma unroll
        for (int nt = 0; nt < 4; nt++) {
            const int n = n0 + nt * 8 + g;
            #pragma unroll
            for (int kt = 0; kt < 4; kt++) {
                const int base = n * 32 + kt * 8 + q;
                bh[nt][kt][0] = BH[base];
                bh[nt][kt][1] = BH[base + 4];
                bl[nt][kt][0] = BL[base];
                bl[nt][kt][1] = BL[base + 4];
            }
        }
    }

    // ldmatrix per-lane base: rows 0-7/8-15 x k-halves
    const int rowoff = (lane & 7) + ((lane >> 3) & 1) * 8;
    const int koff = (lane >> 4) * 16;  // bytes
    const uint32_t sAh_u = smem_u32(sAh);
    const uint32_t sAl_u = smem_u32(sAl);
    const uint32_t lmBase = (uint32_t)(rowoff * APITCH + koff);

    for (int tile = blockIdx.x; tile < ntiles; tile += gridDim.x) {
        const int e0 = tile * 128;
        // ---- stage A tile (hi/lo split) ----
        {
            const int row = tid >> 1, hf = tid & 1;
            const int ge = e0 + row;
            uint32_t* ah = (uint32_t*)(sAh + row * APITCH + hf * 64);
            uint32_t* al = (uint32_t*)(sAl + row * APITCH + hf * 64);
            if (ge < E) {
                const float4* src = (const float4*)(ea + (size_t)ge * 64 + hf * 32);
                #pragma unroll
                for (int j = 0; j < 8; j++) {
                    float4 v = src[j];
                    __nv_bfloat162 h0 = __floats2bfloat162_rn(v.x, v.y);
                    __nv_bfloat162 h1 = __floats2bfloat162_rn(v.z, v.w);
                    __nv_bfloat162 l0 = __floats2bfloat162_rn(v.x - __low2float(h0),
                                                              v.y - __high2float(h0));
                    __nv_bfloat162 l1 = __floats2bfloat162_rn(v.z - __low2float(h1),
                                                              v.w - __high2float(h1));
                    ah[j * 2]     = *(uint32_t*)&h0;
                    ah[j * 2 + 1] = *(uint32_t*)&h1;
                    al[j * 2]     = *(uint32_t*)&l0;
                    al[j * 2 + 1] = *(uint32_t*)&l1;
                }
            } else {
                #pragma unroll
                for (int j = 0; j < 16; j++) { ah[j] = 0u; al[j] = 0u; }
            }
            if (hf == 0) sDst[row] = (ge < E) ? dstv[ge] : -1;
        }
        __syncthreads();

        // ---- mainloop: A hoisted across n-tiles ----
        float acc[8][4][4];
        #pragma unroll
        for (int mt = 0; mt < 8; mt++)
            #pragma unroll
            for (int nt = 0; nt < 4; nt++)
                #pragma unroll
                for (int i = 0; i < 4; i++) acc[mt][nt][i] = 0.f;

        #pragma unroll
        for (int mt = 0; mt < 8; mt++) {
            const uint32_t mtOff = (uint32_t)(mt * 16 * APITCH) + lmBase;
            #pragma unroll
            for (int kt = 0; kt < 4; kt++) {
                uint32_t ah4[4], al4[4];
                ldsm_x4(ah4, sAh_u + mtOff + kt * 32);
                ldsm_x4(al4, sAl_u + mtOff + kt * 32);
                #pragma unroll
                for (int nt = 0; nt < 4; nt++) {
                    mma16816(acc[mt][nt], ah4, bh[nt][kt][0], bh[nt][kt][1]);
                    mma16816(acc[mt][nt], al4, bh[nt][kt][0], bh[nt][kt][1]);
                    mma16816(acc[mt][nt], ah4, bl[nt][kt][0], bl[nt][kt][1]);
                }
            }
        }

        // ---- epilogue: bias + leaky + quad-pack + red4 scatter ----
        #pragma unroll
        for (int mt = 0; mt < 8; mt++) {
            const int rowLo = mt * 16 + g;
            const int dLo = sDst[rowLo], dHi = sDst[rowLo + 8];
            #pragma unroll
            for (int nt = 0; nt < 4; nt++) {
                float* c = acc[mt][nt];
                const int col = n0 + nt * 8 + q * 2;
                const float b0 = sBias[col], b1 = sBias[col + 1];
                float v0 = lk(c[0] + b0), v1 = lk(c[1] + b1);
                float v2 = lk(c[2] + b0), v3 = lk(c[3] + b1);
                float r0 = __shfl_xor_sync(0xffffffffu, v0, 1);
                float r1 = __shfl_xor_sync(0xffffffffu, v1, 1);
                float r2 = __shfl_xor_sync(0xffffffffu, v2, 1);
                float r3 = __shfl_xor_sync(0xffffffffu, v3, 1);
                const int colb = n0 + nt * 8 + (q >> 1) * 4;
                int d;
                float w0, w1, w2, w3;
                if ((q & 1) == 0) { d = dLo; w0 = v0; w1 = v1; w2 = r0; w3 = r1; }
                else              { d = dHi; w0 = r2; w1 = r3; w2 = v2; w3 = v3; }
                if (d >= 0) {
                    float* Sp = (n0 < 128) ? (S1 + (size_t)d * 128 + colb)
                                           : (S2 + (size_t)d * 128 + (colb - 128));
                    red4(Sp, w0, w1, w2, w3);
                }
            }
        }
        __syncthreads();
    }
}

// ======================= node GEMMs (fp32, known-good) =====================
template <int KTOT, bool SECOND, bool DOLEAKY, bool SPLIT>
__global__ __launch_bounds__(256) void node_gemm(
    const float* __restrict__ A1, const float* __restrict__ A2,
    const float* __restrict__ B, const float* __restrict__ bias,
    const float* __restrict__ deg, float* __restrict__ out, int N) {
    extern __shared__ float sm[];
    float* shB = sm;             // [64][128]
    float* shA = sm + 64 * 128;  // [64][64]

    const int tid = threadIdx.x, wid = tid >> 5, lane = tid & 31;
    const int j0 = lane * 4;
    const int row0 = blockIdx.x * 64;

    float degv[8];
    #pragma unroll
    for (int r = 0; r < 8; r++) {
        int row = row0 + wid * 8 + r;
        degv[r] = (SECOND && row < N) ? deg[row] : 1.f;
    }
    float4 bv = *(const float4*)&bias[j0];
    u64 acc[8][2];
    #pragma unroll
    for (int r = 0; r < 8; r++) {
        acc[r][0] = pack2(degv[r] * bv.x, degv[r] * bv.y);
        acc[r][1] = pack2(degv[r] * bv.z, degv[r] * bv.w);
    }

    for (int kc = 0; kc < KTOT; kc += 64) {
        __syncthreads();
        for (int i = tid; i < 2048; i += 256)
            *(float4*)&shB[i * 4] = *(const float4*)&B[(size_t)kc * 128 + i * 4];
        for (int i = tid; i < 1024; i += 256) {
            int rr = i & 63, kq = i >> 6;
            int k4g = kc + kq * 4;
            int row = row0 + rr;
            float4 v = make_float4(0.f, 0.f, 0.f, 0.f);
            if (row < N) {
                if (!SECOND || k4g < 128) {
                    v = *(const float4*)&A1[(size_t)row * 128 + k4g];
                    if (SECOND) {
                        float dg = deg[row];
                        v.x *= dg; v.y *= dg; v.z *= dg; v.w *= dg;
                    }
                } else {
                    v = *(const float4*)&A2[(size_t)row * 128 + (k4g - 128)];
                }
            }
            int k4 = kq * 4;
            shA[(k4 + 0) * 64 + rr] = v.x;
            shA[(k4 + 1) * 64 + rr] = v.y;
            shA[(k4 + 2) * 64 + rr] = v.z;
            shA[(k4 + 3) * 64 + rr] = v.w;
        }
        __syncthreads();

        const float* aBase = shA + wid * 8;
        #pragma unroll 8
        for (int kk = 0; kk < 64; kk++) {
            float4 a03 = *(const float4*)(aBase + kk * 64);
            float4 a47 = *(const float4*)(aBase + kk * 64 + 4);
            ulonglong2 w = *(const ulonglong2*)&shB[kk * 128 + j0];
            float a[8] = {a03.x, a03.y, a03.z, a03.w, a47.x, a47.y, a47.z, a47.w};
            #pragma unroll
            for (int r = 0; r < 8; r++) {
                u64 ad = pack2(a[r], a[r]);
                ffma2(acc[r][0], ad, w.x);
                ffma2(acc[r][1], ad, w.y);
            }
        }
    }

    #pragma unroll
    for (int r = 0; r < 8; r++) {
        int row = row0 + wid * 8 + r;
        if (row >= N) continue;
        float2 p0 = unpack2(acc[r][0]), p1 = unpack2(acc[r][1]);
        float4 v = make_float4(p0.x, p0.y, p1.x, p1.y);
        if (DOLEAKY) { v.x = lk(v.x); v.y = lk(v.y); v.z = lk(v.z); v.w = lk(v.w); }
        if (!SPLIT) {
            *(float4*)&out[(size_t)row * 128 + j0] = v;
        } else {
            if (j0 < 64)
                *(float4*)&out[(size_t)row * 64 + j0] = v;
            else
                *(float4*)&out[(size_t)N * 64 + (size_t)row * 64 + (j0 - 64)] = v;
        }
    }
}

// ---------------------------------------------------------------------------
extern "C" void kernel_launch(void* const* d_in, const int* in_sizes, int n_in,
                              void* d_out, int out_size) {
    const float* x    = (const float*)d_in[0];
    const int*   ei   = (const int*)d_in[1];
    const float* ea   = (const float*)d_in[2];
    const float* e1W1 = (const float*)d_in[3];
    const float* e1b1 = (const float*)d_in[4];
    const float* e1W2 = (const float*)d_in[5];
    const float* e1b2 = (const float*)d_in[6];
    const float* n1W  = (const float*)d_in[7];
    const float* n1b  = (const float*)d_in[8];
    const float* e2W1 = (const float*)d_in[9];
    const float* e2b1 = (const float*)d_in[10];
    const float* e2W2 = (const float*)d_in[11];
    const float* e2b2 = (const float*)d_in[12];
    const float* n2W  = (const float*)d_in[13];
    const float* n2b  = (const float*)d_in[14];
    const float* muW  = (const float*)d_in[15];
    const float* mub  = (const float*)d_in[16];
    const float* lvW  = (const float*)d_in[17];
    const float* lvb  = (const float*)d_in[18];

    const int N = in_sizes[0] / 128;  // 50000
    const int E = in_sizes[2] / 64;   // 640000
    const int* dst = ei + E;          // edge_index row 1

    float *S1, *S2, *h1, *h2, *dg, *B1, *B2, *c1, *c2, *B3, *b3, *biascat;
    __nv_bfloat16 *Bth, *Btl;
    cudaGetSymbolAddress((void**)&S1, g_S1);
    cudaGetSymbolAddress((void**)&S2, g_S2);
    cudaGetSymbolAddress((void**)&h1, g_h1);
    cudaGetSymbolAddress((void**)&h2, g_h2);
    cudaGetSymbolAddress((void**)&dg, g_deg);
    cudaGetSymbolAddress((void**)&B1, g_B1);
    cudaGetSymbolAddress((void**)&B2, g_B2);
    cudaGetSymbolAddress((void**)&c1, g_c1);
    cudaGetSymbolAddress((void**)&c2, g_c2);
    cudaGetSymbolAddress((void**)&B3, g_B3);
    cudaGetSymbolAddress((void**)&b3, g_b3);
    cudaGetSymbolAddress((void**)&Bth, g_Bth);
    cudaGetSymbolAddress((void**)&Btl, g_Btl);
    cudaGetSymbolAddress((void**)&biascat, g_biascat);

    cudaMemsetAsync(S1, 0, (size_t)N * 128 * sizeof(float));
    cudaMemsetAsync(S2, 0, (size_t)N * 128 * sizeof(float));
    cudaMemsetAsync(dg, 0, (size_t)N * sizeof(float));

    prep_all<<<dim3(128, 4), 128>>>(e1W2, e1b2, n1W, n1b,
                                    e2W2, e2b2, n2W, n2b,
                                    muW, mub, lvW, lvb,
                                    e1W1, e1b1, e2W1, e2b1,
                                    B1, c1, B2, c2, B3, b3, Bth, Btl, biascat);
    deg_kernel<<<(E + 255) / 256, 256>>>(dst, dg, E);

    int ntiles = (E + 127) / 128;
    int egrid = ntiles < 148 ? ntiles : 148;
    edge_mma_kernel<<<egrid, 256>>>(ea, dst, Bth, Btl, biascat, S1, S2, E, ntiles);

    const int NODE_SMEM = (64 * 128 + 64 * 64) * 4;  // 49152 B
    int nblk = (N + 63) / 64;
    cudaFuncSetAttribute(node_gemm<256, true, true, false>,
                         cudaFuncAttributeMaxDynamicSharedMemorySize, NODE_SMEM);
    cudaFuncSetAttribute(node_gemm<128, false, false, true>,
                         cudaFuncAttributeMaxDynamicSharedMemorySize, NODE_SMEM);

    node_gemm<256, true, true, false><<<nblk, 256, NODE_SMEM>>>(x,  S1, B1, c1, dg, h1, N);
    node_gemm<256, true, true, false><<<nblk, 256, NODE_SMEM>>>(h1, S2, B2, c2, dg, h2, N);
    node_gemm<128, false, false, true><<<nblk, 256, NODE_SMEM>>>(h2, nullptr, B3, b3, nullptr,
                                                                 (float*)d_out, N);
}